// round 6
// baseline (speedup 1.0000x reference)
#include <cuda_runtime.h>
#include <math.h>

#define B_    64
#define HID   1536
#define NH    12
#define NKV   2
#define HD    128
#define G_    6
#define INTER 8960
#define MAXB  256
#define BSZ   16
#define NBLK  16384
#define QSZ   1536
#define KVSZ  256
#define QKVN  2048
#define EPS_  1e-6f
#define SCALE 0.08838834764831845f   // 1/sqrt(128)

typedef unsigned long long ull;

__device__ __forceinline__ void fma2(ull &d, ull a, ull b) {
    asm("fma.rn.f32x2 %0, %1, %2, %3;" : "=l"(d) : "l"(a), "l"(b), "l"(d));
}
__device__ __forceinline__ float2 unpack2(ull v) {
    float2 r; asm("mov.b64 {%0, %1}, %2;" : "=f"(r.x), "=f"(r.y) : "l"(v)); return r;
}

// ---------------- scratch (device globals; no allocation allowed) ----------
__device__ float g_res1[B_*HID];
__device__ float g_hn  [B_*HID];
__device__ float g_hn2 [B_*HID];
__device__ float g_qkv [B_*QKVN];
__device__ float g_attn[B_*QSZ];
__device__ float g_tmp [B_*HID];
__device__ float g_act [B_*INTER];
__device__ float g_part[2*B_*2*INTER];   // split-K partials (max 2*64*17920)

// ---------------- fused add + RMSNorm -------------------------------------
__global__ void __launch_bounds__(256)
addnorm_kernel(const float* __restrict__ x, const float* __restrict__ y,
               const float* __restrict__ w,
               float* __restrict__ res, float* __restrict__ nout)
{
    int b = blockIdx.x, tid = threadIdx.x;
    const float* xr = x + b*HID;
    const float* yr = y + b*HID;
    float v[6];
    float ss = 0.f;
#pragma unroll
    for (int t = 0; t < 6; t++) {
        int i = tid + t*256;
        float s = xr[i] + yr[i];
        v[t] = s;
        ss += s*s;
    }
    __shared__ float red[8];
#pragma unroll
    for (int o = 16; o; o >>= 1) ss += __shfl_xor_sync(~0u, ss, o);
    if ((tid & 31) == 0) red[tid >> 5] = ss;
    __syncthreads();
    if (tid < 8) {
        float t2 = red[tid];
#pragma unroll
        for (int o = 4; o; o >>= 1) t2 += __shfl_xor_sync(0xffu, t2, o);
        if (tid == 0) red[0] = t2;
    }
    __syncthreads();
    float inv = rsqrtf(red[0] * (1.0f/HID) + EPS_);
#pragma unroll
    for (int t = 0; t < 6; t++) {
        int i = tid + t*256;
        res[b*HID + i]  = v[t];
        nout[b*HID + i] = v[t] * inv * w[i];
    }
}

// ---------------- FFMA2 SGEMM: C[64,N] = A[64,K] @ B[K,N] ------------------
// 64x128 tile, 4x8 outputs/thread packed as f32x2, double-buffered smem,
// A staged pre-broadcast (float2 duplicated) so inner loop is pure LDS+FFMA2.
// grid.x tiles N by 128; grid.y = split-K slab; partials at C + y*64*N.
__global__ void __launch_bounds__(256)
gemm_f2(const float* __restrict__ A, const float* __restrict__ B,
        float* __restrict__ C, int K, int N, int klen)
{
    __shared__ __align__(16) float2 Asd[2][16][64];
    __shared__ __align__(16) float  Bs [2][16][128];
    const int tid = threadIdx.x;
    const int n0 = blockIdx.x * 128;
    const int k0 = blockIdx.y * klen;
    float* Cp = C + (size_t)blockIdx.y * 64 * N;

    const int arow = tid >> 2, akq = (tid & 3) * 4;   // A: 1 float4 each
    const int bk   = tid >> 5, bc  = (tid & 31) * 4;  // B: 2 float4 each
    const int tr   = tid >> 4, tc  = tid & 15;        // output 4 rows x 8 cols

    const float* Aptr  = A + (size_t)arow*K + k0 + akq;
    const float* Bptr0 = B + (size_t)(k0 + bk)*N + n0 + bc;
    const float* Bptr1 = B + (size_t)(k0 + bk + 8)*N + n0 + bc;

    float4 av  = *(const float4*)Aptr;
    float4 b0v = *(const float4*)Bptr0;
    float4 b1v = *(const float4*)Bptr1;

    Asd[0][akq+0][arow] = make_float2(av.x, av.x);
    Asd[0][akq+1][arow] = make_float2(av.y, av.y);
    Asd[0][akq+2][arow] = make_float2(av.z, av.z);
    Asd[0][akq+3][arow] = make_float2(av.w, av.w);
    *(float4*)&Bs[0][bk  ][bc] = b0v;
    *(float4*)&Bs[0][bk+8][bc] = b1v;
    __syncthreads();

    ull acc[4][4];
#pragma unroll
    for (int i = 0; i < 4; i++)
#pragma unroll
        for (int j = 0; j < 4; j++) acc[i][j] = 0ull;

    const int nk = klen >> 4;
    int buf = 0;
    for (int kt = 0; kt < nk; kt++) {
        float4 avn, b0n, b1n;
        if (kt + 1 < nk) {
            avn = *(const float4*)(Aptr + (kt+1)*16);
            b0n = *(const float4*)(Bptr0 + (size_t)(kt+1)*16*N);
            b1n = *(const float4*)(Bptr1 + (size_t)(kt+1)*16*N);
        }
#pragma unroll
        for (int kk = 0; kk < 16; kk++) {
            const ull* ap = (const ull*)&Asd[buf][kk][tr*4];
            const ull* bp = (const ull*)&Bs [buf][kk][tc*8];
            ull a0 = ap[0], a1 = ap[1], a2 = ap[2], a3 = ap[3];
            ull b0 = bp[0], b1 = bp[1], b2 = bp[2], b3 = bp[3];
            fma2(acc[0][0], a0, b0); fma2(acc[0][1], a0, b1);
            fma2(acc[0][2], a0, b2); fma2(acc[0][3], a0, b3);
            fma2(acc[1][0], a1, b0); fma2(acc[1][1], a1, b1);
            fma2(acc[1][2], a1, b2); fma2(acc[1][3], a1, b3);
            fma2(acc[2][0], a2, b0); fma2(acc[2][1], a2, b1);
            fma2(acc[2][2], a2, b2); fma2(acc[2][3], a2, b3);
            fma2(acc[3][0], a3, b0); fma2(acc[3][1], a3, b1);
            fma2(acc[3][2], a3, b2); fma2(acc[3][3], a3, b3);
        }
        if (kt + 1 < nk) {
            int nb = buf ^ 1;
            Asd[nb][akq+0][arow] = make_float2(avn.x, avn.x);
            Asd[nb][akq+1][arow] = make_float2(avn.y, avn.y);
            Asd[nb][akq+2][arow] = make_float2(avn.z, avn.z);
            Asd[nb][akq+3][arow] = make_float2(avn.w, avn.w);
            *(float4*)&Bs[nb][bk  ][bc] = b0n;
            *(float4*)&Bs[nb][bk+8][bc] = b1n;
            __syncthreads();
            buf = nb;
        }
    }
#pragma unroll
    for (int r = 0; r < 4; r++) {
        float2 c0 = unpack2(acc[r][0]);
        float2 c1 = unpack2(acc[r][1]);
        float2 c2 = unpack2(acc[r][2]);
        float2 c3 = unpack2(acc[r][3]);
        float* crow = Cp + (size_t)(tr*4 + r)*N + n0 + tc*8;
        *(float4*)(crow)     = make_float4(c0.x, c0.y, c1.x, c1.y);
        *(float4*)(crow + 4) = make_float4(c2.x, c2.y, c3.x, c3.y);
    }
}

// ---------------- split-K reduce (+ optional bias) -------------------------
__global__ void __launch_bounds__(256)
reduce_kernel(const float* __restrict__ part, const float* __restrict__ bias,
              float* __restrict__ out, int MN, int N, int S)
{
    int i = blockIdx.x*256 + threadIdx.x;
    if (i >= MN) return;
    float s = bias ? bias[i % N] : 0.f;
    for (int p = 0; p < S; p++) s += part[(size_t)p*MN + i];
    out[i] = s;
}

// ---------------- fused split-K reduce + SwiGLU for gate_up ---------------
// part holds S slabs of [64, 2*INTER]; out[b][c] = silu(gate)*up.
__global__ void __launch_bounds__(256)
act_reduce_kernel(const float* __restrict__ part, float* __restrict__ out, int S)
{
    int i = blockIdx.x*256 + threadIdx.x;
    if (i >= B_*INTER) return;
    int b = i / INTER, c = i - b*INTER;
    size_t gi = (size_t)b*2*INTER + c;
    size_t ui = gi + INTER;
    float g = 0.f, u = 0.f;
    for (int p = 0; p < S; p++) {
        g += part[(size_t)p*B_*2*INTER + gi];
        u += part[(size_t)p*B_*2*INTER + ui];
    }
    out[i] = (g / (1.f + __expf(-g))) * u;
}

// ---------------- NEOX RoPE (in place on q & k of qkv) ---------------------
__global__ void __launch_bounds__(256)
rope_kernel(float* __restrict__ qkv, const int* __restrict__ positions)
{
    int b = blockIdx.x;
    float pos = (float)positions[b];
    for (int idx = threadIdx.x; idx < (NH + NKV)*64; idx += 256) {
        int head = idx >> 6, d = idx & 63;
        float inv = exp2f((float)d * (-19.931568569324174f/64.0f)); // theta^-d/64
        float ang = pos * inv;
        float s, c;
        sincosf(ang, &s, &c);
        float* p = qkv + b*QKVN + (head < NH ? head*HD : QSZ + (head - NH)*HD);
        float x1 = p[d], x2 = p[d+64];
        p[d]    = x1*c - x2*s;
        p[d+64] = x2*c + x1*s;
    }
}

// ---------------- GQA paged decode attention -------------------------------
// block = (b, kv_head). 8 warps stride the key sequence with a depth-4
// register prefetch ring (8 LDG.128 in flight per warp). New token's k/v
// substituted at read time (cache never written).
__global__ void __launch_bounds__(256)
attn_kernel(const float* __restrict__ qkv, const float* __restrict__ kvc,
            const int* __restrict__ bt_all, const int* __restrict__ slot_map,
            const int* __restrict__ seq_lens, float* __restrict__ out)
{
    const int b    = blockIdx.x >> 1;
    const int kvh  = blockIdx.x & 1;
    const int warp = threadIdx.x >> 5;
    const int lane = threadIdx.x & 31;
    const int len  = seq_lens[b];
    const int smap = slot_map[b];
    const int* bt  = bt_all + b*MAXB;

    const float* kc   = kvc;
    const float* vc   = kvc + (size_t)NBLK*BSZ*NKV*HD;
    const float* knew = qkv + b*QKVN + QSZ + kvh*HD;
    const float* vnew = qkv + b*QKVN + QSZ + KVSZ + kvh*HD;

    float q[G_][4];
#pragma unroll
    for (int h = 0; h < G_; h++) {
        float4 qv = *(const float4*)(qkv + b*QKVN + (kvh*G_ + h)*HD + lane*4);
        q[h][0] = qv.x*SCALE; q[h][1] = qv.y*SCALE;
        q[h][2] = qv.z*SCALE; q[h][3] = qv.w*SCALE;
    }

    float m[G_], l[G_], acc[G_][4];
#pragma unroll
    for (int h = 0; h < G_; h++) {
        m[h] = -1e30f; l[h] = 0.f;
        acc[h][0] = acc[h][1] = acc[h][2] = acc[h][3] = 0.f;
    }

    float4 kbuf[4], vbuf[4];
#pragma unroll
    for (int d = 0; d < 4; d++) {
        int j = warp + d*8;
        kbuf[d] = make_float4(0,0,0,0);
        vbuf[d] = make_float4(0,0,0,0);
        if (j < len) {
            int slot = bt[j >> 4]*BSZ + (j & 15);
            const float *kp, *vp;
            if (slot == smap) { kp = knew; vp = vnew; }
            else {
                size_t off = ((size_t)slot*NKV + kvh)*HD;
                kp = kc + off; vp = vc + off;
            }
            kbuf[d] = *(const float4*)(kp + lane*4);
            vbuf[d] = *(const float4*)(vp + lane*4);
        }
    }

    for (int j0 = warp; j0 < len; j0 += 32) {
#pragma unroll
        for (int d = 0; d < 4; d++) {
            int j = j0 + d*8;
            if (j >= len) break;
            float4 kf = kbuf[d], vf = vbuf[d];
            int jp = j + 32;
            if (jp < len) {
                int slot = bt[jp >> 4]*BSZ + (jp & 15);
                const float *kp, *vp;
                if (slot == smap) { kp = knew; vp = vnew; }
                else {
                    size_t off = ((size_t)slot*NKV + kvh)*HD;
                    kp = kc + off; vp = vc + off;
                }
                kbuf[d] = *(const float4*)(kp + lane*4);
                vbuf[d] = *(const float4*)(vp + lane*4);
            }

            float s[G_];
#pragma unroll
            for (int h = 0; h < G_; h++)
                s[h] = q[h][0]*kf.x + q[h][1]*kf.y + q[h][2]*kf.z + q[h][3]*kf.w;
#pragma unroll
            for (int o = 16; o; o >>= 1) {
#pragma unroll
                for (int h = 0; h < G_; h++)
                    s[h] += __shfl_xor_sync(~0u, s[h], o);
            }
#pragma unroll
            for (int h = 0; h < G_; h++) {
                if (s[h] > m[h]) {   // warp-uniform branch
                    float corr = __expf(m[h] - s[h]);
                    l[h] = l[h]*corr + 1.f;
                    acc[h][0] = acc[h][0]*corr + vf.x;
                    acc[h][1] = acc[h][1]*corr + vf.y;
                    acc[h][2] = acc[h][2]*corr + vf.z;
                    acc[h][3] = acc[h][3]*corr + vf.w;
                    m[h] = s[h];
                } else {
                    float p = __expf(s[h] - m[h]);
                    l[h] += p;
                    acc[h][0] += p*vf.x;
                    acc[h][1] += p*vf.y;
                    acc[h][2] += p*vf.z;
                    acc[h][3] += p*vf.w;
                }
            }
        }
    }

    // combine 8 warps (logsumexp merge)
    __shared__ float s_acc[8][G_][HD];
    __shared__ float s_m[8][G_], s_l[8][G_], s_w[8][G_], s_L[G_];
#pragma unroll
    for (int h = 0; h < G_; h++) {
        s_acc[warp][h][lane*4+0] = acc[h][0];
        s_acc[warp][h][lane*4+1] = acc[h][1];
        s_acc[warp][h][lane*4+2] = acc[h][2];
        s_acc[warp][h][lane*4+3] = acc[h][3];
        if (lane == 0) { s_m[warp][h] = m[h]; s_l[warp][h] = l[h]; }
    }
    __syncthreads();
    if (threadIdx.x < G_) {
        int h = threadIdx.x;
        float M = -1e30f;
#pragma unroll
        for (int w = 0; w < 8; w++) M = fmaxf(M, s_m[w][h]);
        float L = 0.f;
#pragma unroll
        for (int w = 0; w < 8; w++) {
            float wt = __expf(s_m[w][h] - M);
            s_w[w][h] = wt;
            L += wt * s_l[w][h];
        }
        s_L[h] = 1.f / L;
    }
    __syncthreads();
    for (int idx = threadIdx.x; idx < G_*HD; idx += 256) {
        int h = idx >> 7, d = idx & 127;
        float o = 0.f;
#pragma unroll
        for (int w = 0; w < 8; w++) o += s_w[w][h] * s_acc[w][h][d];
        out[b*QSZ + (kvh*G_ + h)*HD + d] = o * s_L[h];
    }
}

// ---------------- launch ----------------------------------------------------
extern "C" void kernel_launch(void* const* d_in, const int* in_sizes, int n_in,
                              void* d_out, int out_size)
{
    const int*   positions    = (const int*)  d_in[0];
    const float* hidden       = (const float*)d_in[1];
    const float* residual     = (const float*)d_in[2];
    const float* kv_cache     = (const float*)d_in[3];
    const int*   block_tables = (const int*)  d_in[4];
    const int*   slot_mapping = (const int*)  d_in[5];
    const int*   seq_lens     = (const int*)  d_in[6];
    // d_in[7] = is_prefill (statically 0)
    const float* w_qkv = (const float*)d_in[8];
    const float* b_qkv = (const float*)d_in[9];
    const float* w_o   = (const float*)d_in[10];
    const float* ln1   = (const float*)d_in[11];
    const float* ln2   = (const float*)d_in[12];
    const float* w_gu  = (const float*)d_in[13];
    const float* w_dn  = (const float*)d_in[14];
    float* out = (float*)d_out;   // [h (B*HID) | res2 (B*HID)]

    float *res1, *hn, *hn2, *qkv, *attn, *tmp, *act, *part;
    cudaGetSymbolAddress((void**)&res1, g_res1);
    cudaGetSymbolAddress((void**)&hn,   g_hn);
    cudaGetSymbolAddress((void**)&hn2,  g_hn2);
    cudaGetSymbolAddress((void**)&qkv,  g_qkv);
    cudaGetSymbolAddress((void**)&attn, g_attn);
    cudaGetSymbolAddress((void**)&tmp,  g_tmp);
    cudaGetSymbolAddress((void**)&act,  g_act);
    cudaGetSymbolAddress((void**)&part, g_part);

    // 1. res1 = hidden + residual ; hn = rmsnorm(res1)*ln1
    addnorm_kernel<<<B_, 256>>>(hidden, residual, ln1, res1, hn);

    // 2. qkv = hn @ w_qkv + b_qkv   (split-K 16: 256 blocks, klen 96)
    gemm_f2<<<dim3(QKVN/128, 16), 256>>>(hn, w_qkv, part, HID, QKVN, 96);
    reduce_kernel<<<(B_*QKVN + 255)/256, 256>>>(part, b_qkv, qkv, B_*QKVN, QKVN, 16);

    // 3. RoPE on q, k (in place)
    rope_kernel<<<B_, 256>>>(qkv, positions);

    // 4. paged GQA decode attention
    attn_kernel<<<B_*NKV, 256>>>(qkv, kv_cache, block_tables, slot_mapping,
                                 seq_lens, attn);

    // 5. o-proj (split-K 12: 144 blocks, klen 128)
    gemm_f2<<<dim3(HID/128, 12), 256>>>(attn, w_o, part, QSZ, HID, 128);
    reduce_kernel<<<(B_*HID + 255)/256, 256>>>(part, nullptr, tmp, B_*HID, HID, 12);

    // 6. res2 = o + res1 (-> out second half) ; hn2 = rmsnorm(res2)*ln2
    addnorm_kernel<<<B_, 256>>>(tmp, res1, ln2, out + B_*HID, hn2);

    // 7. gate_up GEMM (split-K 2: 280 blocks, klen 768) + fused reduce+SwiGLU
    gemm_f2<<<dim3(2*INTER/128, 2), 256>>>(hn2, w_gu, part, HID, 2*INTER, 768);
    act_reduce_kernel<<<(B_*INTER + 255)/256, 256>>>(part, act, 2);

    // 8. down GEMM (split-K 20: 240 blocks, klen 448) -> out first half
    gemm_f2<<<dim3(HID/128, 20), 256>>>(act, w_dn, part, INTER, HID, 448);
    reduce_kernel<<<(B_*HID + 255)/256, 256>>>(part, nullptr, out, B_*HID, HID, 20);
}

// round 10
// speedup vs baseline: 1.3849x; 1.3849x over previous
#include <cuda_runtime.h>
#include <math.h>

#define B_    64
#define HID   1536
#define NH    12
#define NKV   2
#define HD    128
#define G_    6
#define INTER 8960
#define MAXB  256
#define BSZ   16
#define NBLK  16384
#define QSZ   1536
#define KVSZ  256
#define QKVN  2048
#define EPS_  1e-6f
#define SCALE 0.08838834764831845f   // 1/sqrt(128)
#define NW    16                     // warps per attention block

// ---------------- scratch (device globals; no allocation allowed) ----------
__device__ float g_res1[B_*HID];
__device__ float g_hn  [B_*HID];
__device__ float g_hn2 [B_*HID];
__device__ float g_qkv [B_*QKVN];
__device__ float g_attn[B_*QSZ];
__device__ float g_tmp [B_*HID];
__device__ float g_act [B_*INTER];
__device__ float g_part[2097152];    // split-K partials

// ---------------- fused add + RMSNorm -------------------------------------
__global__ void __launch_bounds__(256)
addnorm_kernel(const float* __restrict__ x, const float* __restrict__ y,
               const float* __restrict__ w,
               float* __restrict__ res, float* __restrict__ nout)
{
    int b = blockIdx.x, tid = threadIdx.x;
    const float* xr = x + b*HID;
    const float* yr = y + b*HID;
    float v[6];
    float ss = 0.f;
#pragma unroll
    for (int t = 0; t < 6; t++) {
        int i = tid + t*256;
        float s = xr[i] + yr[i];
        v[t] = s;
        ss += s*s;
    }
    __shared__ float red[8];
#pragma unroll
    for (int o = 16; o; o >>= 1) ss += __shfl_xor_sync(~0u, ss, o);
    if ((tid & 31) == 0) red[tid >> 5] = ss;
    __syncthreads();
    if (tid < 8) {
        float t2 = red[tid];
#pragma unroll
        for (int o = 4; o; o >>= 1) t2 += __shfl_xor_sync(0xffu, t2, o);
        if (tid == 0) red[0] = t2;
    }
    __syncthreads();
    float inv = rsqrtf(red[0] * (1.0f/HID) + EPS_);
#pragma unroll
    for (int t = 0; t < 6; t++) {
        int i = tid + t*256;
        res[b*HID + i]  = v[t];
        nout[b*HID + i] = v[t] * inv * w[i];
    }
}

// ---------------- SGEMM: C[64,N] = A[64,K] @ B[K,N] ------------------------
// 64x128 tile, 4 rows x 8 cols fp32 per thread (32 FFMA / 3 LDS.128 per k),
// double-buffered smem, one barrier per 16-k tile. A rows padded to 68 floats
// (272 B: multiple of 16 -> float4-aligned; 68 mod 32 = 4 -> spread stores).
__global__ void __launch_bounds__(256)
gemm_f32(const float* __restrict__ A, const float* __restrict__ B,
         float* __restrict__ C, int K, int N, int klen)
{
    __shared__ __align__(16) float As[2][16][68];
    __shared__ __align__(16) float Bs[2][16][128];
    const int tid = threadIdx.x;
    const int n0 = blockIdx.x * 128;
    const int k0 = blockIdx.y * klen;
    float* Cp = C + (size_t)blockIdx.y * 64 * N;

    const int arow = tid >> 2, akq = (tid & 3) * 4;   // A: 1 float4 each
    const int bk   = tid >> 5, bc  = (tid & 31) * 4;  // B: 2 float4 each
    const int tr   = tid >> 4, tc  = tid & 15;        // out: 4 rows x 8 cols

    const float* Aptr  = A + (size_t)arow*K + k0 + akq;
    const float* Bptr0 = B + (size_t)(k0 + bk)*N + n0 + bc;
    const float* Bptr1 = B + (size_t)(k0 + bk + 8)*N + n0 + bc;

    float4 av  = *(const float4*)Aptr;
    float4 b0v = *(const float4*)Bptr0;
    float4 b1v = *(const float4*)Bptr1;

    As[0][akq+0][arow] = av.x;
    As[0][akq+1][arow] = av.y;
    As[0][akq+2][arow] = av.z;
    As[0][akq+3][arow] = av.w;
    *(float4*)&Bs[0][bk  ][bc] = b0v;
    *(float4*)&Bs[0][bk+8][bc] = b1v;
    __syncthreads();

    float acc[4][8];
#pragma unroll
    for (int i = 0; i < 4; i++)
#pragma unroll
        for (int j = 0; j < 8; j++) acc[i][j] = 0.f;

    const int nk = klen >> 4;
    int buf = 0;
    for (int kt = 0; kt < nk; kt++) {
        float4 avn, b0n, b1n;
        if (kt + 1 < nk) {
            avn = *(const float4*)(Aptr + (kt+1)*16);
            b0n = *(const float4*)(Bptr0 + (size_t)(kt+1)*16*N);
            b1n = *(const float4*)(Bptr1 + (size_t)(kt+1)*16*N);
        }
#pragma unroll
        for (int kk = 0; kk < 16; kk++) {
            float4 a  = *(const float4*)&As[buf][kk][tr*4];
            float4 b0 = *(const float4*)&Bs[buf][kk][tc*8];
            float4 b1 = *(const float4*)&Bs[buf][kk][tc*8+4];
            acc[0][0] += a.x*b0.x; acc[0][1] += a.x*b0.y; acc[0][2] += a.x*b0.z; acc[0][3] += a.x*b0.w;
            acc[0][4] += a.x*b1.x; acc[0][5] += a.x*b1.y; acc[0][6] += a.x*b1.z; acc[0][7] += a.x*b1.w;
            acc[1][0] += a.y*b0.x; acc[1][1] += a.y*b0.y; acc[1][2] += a.y*b0.z; acc[1][3] += a.y*b0.w;
            acc[1][4] += a.y*b1.x; acc[1][5] += a.y*b1.y; acc[1][6] += a.y*b1.z; acc[1][7] += a.y*b1.w;
            acc[2][0] += a.z*b0.x; acc[2][1] += a.z*b0.y; acc[2][2] += a.z*b0.z; acc[2][3] += a.z*b0.w;
            acc[2][4] += a.z*b1.x; acc[2][5] += a.z*b1.y; acc[2][6] += a.z*b1.z; acc[2][7] += a.z*b1.w;
            acc[3][0] += a.w*b0.x; acc[3][1] += a.w*b0.y; acc[3][2] += a.w*b0.z; acc[3][3] += a.w*b0.w;
            acc[3][4] += a.w*b1.x; acc[3][5] += a.w*b1.y; acc[3][6] += a.w*b1.z; acc[3][7] += a.w*b1.w;
        }
        if (kt + 1 < nk) {
            int nb = buf ^ 1;
            As[nb][akq+0][arow] = avn.x;
            As[nb][akq+1][arow] = avn.y;
            As[nb][akq+2][arow] = avn.z;
            As[nb][akq+3][arow] = avn.w;
            *(float4*)&Bs[nb][bk  ][bc] = b0n;
            *(float4*)&Bs[nb][bk+8][bc] = b1n;
            __syncthreads();
            buf = nb;
        }
    }
#pragma unroll
    for (int r = 0; r < 4; r++) {
        float* crow = Cp + (size_t)(tr*4 + r)*N + n0 + tc*8;
        *(float4*)(crow)     = make_float4(acc[r][0], acc[r][1], acc[r][2], acc[r][3]);
        *(float4*)(crow + 4) = make_float4(acc[r][4], acc[r][5], acc[r][6], acc[r][7]);
    }
}

// ---------------- split-K reduce (+ optional bias) -------------------------
__global__ void __launch_bounds__(256)
reduce_kernel(const float* __restrict__ part, const float* __restrict__ bias,
              float* __restrict__ out, int MN, int N, int S)
{
    int i = blockIdx.x*256 + threadIdx.x;
    if (i >= MN) return;
    float s = bias ? bias[i % N] : 0.f;
    for (int p = 0; p < S; p++) s += part[(size_t)p*MN + i];
    out[i] = s;
}

// ---------------- fused qkv: split-K reduce + bias + NEOX RoPE -------------
__global__ void __launch_bounds__(256)
qkv_finish_kernel(const float* __restrict__ part, const float* __restrict__ bias,
                  const int* __restrict__ positions, float* __restrict__ qkv, int S)
{
    const int b = blockIdx.x, tid = threadIdx.x;
    const float pos = (float)positions[b];
    const int MN = B_*QKVN;
#pragma unroll
    for (int t = 0; t < 4; t++) {
        int p = tid + t*256;            // pair index 0..1023
        int chunk = p >> 6, d = p & 63;
        int c0 = chunk*128 + d;
        int c1 = c0 + 64;
        float s0 = bias[c0], s1 = bias[c1];
        for (int s = 0; s < S; s++) {
            const float* pp = part + (size_t)s*MN + b*QKVN;
            s0 += pp[c0];
            s1 += pp[c1];
        }
        if (chunk < NH + NKV) {
            float inv = exp2f((float)d * (-19.931568569324174f/64.0f)); // theta^-d/64
            float sn, cs;
            sincosf(pos * inv, &sn, &cs);
            float r0 = s0*cs - s1*sn;
            float r1 = s1*cs + s0*sn;
            s0 = r0; s1 = r1;
        }
        qkv[b*QKVN + c0] = s0;
        qkv[b*QKVN + c1] = s1;
    }
}

// ---------------- GQA paged decode attention -------------------------------
// block = (b, kv_head), 512 threads / 16 warps, depth-4 register prefetch
// ring (8 LDG.128 in flight per warp -> 128 per block). Online softmax per
// warp for 6 GQA heads; logsumexp tree merge in smem. New token's k/v
// substituted at read time (cache never written).
__global__ void __launch_bounds__(512)
attn_kernel(const float* __restrict__ qkv, const float* __restrict__ kvc,
            const int* __restrict__ bt_all, const int* __restrict__ slot_map,
            const int* __restrict__ seq_lens, float* __restrict__ out)
{
    const int b    = blockIdx.x >> 1;
    const int kvh  = blockIdx.x & 1;
    const int warp = threadIdx.x >> 5;
    const int lane = threadIdx.x & 31;
    const int len  = seq_lens[b];
    const int smap = slot_map[b];
    const int* bt  = bt_all + b*MAXB;

    const float* kc   = kvc;
    const float* vc   = kvc + (size_t)NBLK*BSZ*NKV*HD;
    const float* knew = qkv + b*QKVN + QSZ + kvh*HD;
    const float* vnew = qkv + b*QKVN + QSZ + KVSZ + kvh*HD;

    float q[G_][4];
#pragma unroll
    for (int h = 0; h < G_; h++) {
        float4 qv = *(const float4*)(qkv + b*QKVN + (kvh*G_ + h)*HD + lane*4);
        q[h][0] = qv.x*SCALE; q[h][1] = qv.y*SCALE;
        q[h][2] = qv.z*SCALE; q[h][3] = qv.w*SCALE;
    }

    float m[G_], l[G_], acc[G_][4];
#pragma unroll
    for (int h = 0; h < G_; h++) {
        m[h] = -1e30f; l[h] = 0.f;
        acc[h][0] = acc[h][1] = acc[h][2] = acc[h][3] = 0.f;
    }

    float4 kbuf[4], vbuf[4];
#pragma unroll
    for (int d = 0; d < 4; d++) {
        int j = warp + d*NW;
        kbuf[d] = make_float4(0,0,0,0);
        vbuf[d] = make_float4(0,0,0,0);
        if (j < len) {
            int slot = bt[j >> 4]*BSZ + (j & 15);
            const float *kp, *vp;
            if (slot == smap) { kp = knew; vp = vnew; }
            else {
                size_t off = ((size_t)slot*NKV + kvh)*HD;
                kp = kc + off; vp = vc + off;
            }
            kbuf[d] = *(const float4*)(kp + lane*4);
            vbuf[d] = *(const float4*)(vp + lane*4);
        }
    }

    for (int j0 = warp; j0 < len; j0 += NW*4) {
#pragma unroll
        for (int d = 0; d < 4; d++) {
            int j = j0 + d*NW;
            if (j >= len) break;
            float4 kf = kbuf[d], vf = vbuf[d];
            int jp = j + NW*4;
            if (jp < len) {
                int slot = bt[jp >> 4]*BSZ + (jp & 15);
                const float *kp, *vp;
                if (slot == smap) { kp = knew; vp = vnew; }
                else {
                    size_t off = ((size_t)slot*NKV + kvh)*HD;
                    kp = kc + off; vp = vc + off;
                }
                kbuf[d] = *(const float4*)(kp + lane*4);
                vbuf[d] = *(const float4*)(vp + lane*4);
            }

            float s[G_];
#pragma unroll
            for (int h = 0; h < G_; h++)
                s[h] = q[h][0]*kf.x + q[h][1]*kf.y + q[h][2]*kf.z + q[h][3]*kf.w;
#pragma unroll
            for (int o = 16; o; o >>= 1) {
#pragma unroll
                for (int h = 0; h < G_; h++)
                    s[h] += __shfl_xor_sync(~0u, s[h], o);
            }
#pragma unroll
            for (int h = 0; h < G_; h++) {
                if (s[h] > m[h]) {   // warp-uniform branch
                    float corr = __expf(m[h] - s[h]);
                    l[h] = l[h]*corr + 1.f;
                    acc[h][0] = acc[h][0]*corr + vf.x;
                    acc[h][1] = acc[h][1]*corr + vf.y;
                    acc[h][2] = acc[h][2]*corr + vf.z;
                    acc[h][3] = acc[h][3]*corr + vf.w;
                    m[h] = s[h];
                } else {
                    float p = __expf(s[h] - m[h]);
                    l[h] += p;
                    acc[h][0] += p*vf.x;
                    acc[h][1] += p*vf.y;
                    acc[h][2] += p*vf.z;
                    acc[h][3] += p*vf.w;
                }
            }
        }
    }

    // ---- merge 16 warps: logsumexp weights, then tree merge in smem ----
    __shared__ float s_m[NW][G_], s_l[NW][G_], s_w[NW][G_], s_L[G_];
    __shared__ float s_buf[8][G_][HD];   // 24 KB
    if (lane == 0) {
#pragma unroll
        for (int h = 0; h < G_; h++) { s_m[warp][h] = m[h]; s_l[warp][h] = l[h]; }
    }
    __syncthreads();
    if (threadIdx.x < G_) {
        int h = threadIdx.x;
        float M = -1e30f;
#pragma unroll
        for (int w = 0; w < NW; w++) M = fmaxf(M, s_m[w][h]);
        float L = 0.f;
#pragma unroll
        for (int w = 0; w < NW; w++) {
            float wt = __expf(s_m[w][h] - M);
            s_w[w][h] = wt;
            L += wt * s_l[w][h];
        }
        s_L[h] = 1.f / L;
    }
    __syncthreads();
    if (warp >= 8) {
#pragma unroll
        for (int h = 0; h < G_; h++) {
            float wt = s_w[warp][h];
#pragma unroll
            for (int i = 0; i < 4; i++)
                s_buf[warp-8][h][lane*4+i] = wt * acc[h][i];
        }
    }
    __syncthreads();
    if (warp < 8) {
#pragma unroll
        for (int h = 0; h < G_; h++) {
            float wt = s_w[warp][h];
#pragma unroll
            for (int i = 0; i < 4; i++)
                s_buf[warp][h][lane*4+i] += wt * acc[h][i];
        }
    }
    __syncthreads();
    if (warp < 4) {
#pragma unroll
        for (int h = 0; h < G_; h++)
#pragma unroll
            for (int i = 0; i < 4; i++)
                s_buf[warp][h][lane*4+i] += s_buf[warp+4][h][lane*4+i];
    }
    __syncthreads();
    if (warp < 2) {
#pragma unroll
        for (int h = 0; h < G_; h++)
#pragma unroll
            for (int i = 0; i < 4; i++)
                s_buf[warp][h][lane*4+i] += s_buf[warp+2][h][lane*4+i];
    }
    __syncthreads();
    if (warp == 0) {
#pragma unroll
        for (int h = 0; h < G_; h++)
#pragma unroll
            for (int i = 0; i < 4; i++)
                s_buf[0][h][lane*4+i] += s_buf[1][h][lane*4+i];
    }
    __syncthreads();
    for (int idx = threadIdx.x; idx < G_*HD; idx += 512) {
        int h = idx >> 7, d = idx & 127;
        out[b*QSZ + (kvh*G_ + h)*HD + d] = s_buf[0][h][d] * s_L[h];
    }
}

// ---------------- fused split-K reduce + SwiGLU for gate_up ---------------
__global__ void __launch_bounds__(256)
act_reduce_kernel(const float* __restrict__ part, float* __restrict__ out, int S)
{
    int i = blockIdx.x*256 + threadIdx.x;
    if (i >= B_*INTER) return;
    int b = i / INTER, c = i - b*INTER;
    size_t gi = (size_t)b*2*INTER + c;
    size_t ui = gi + INTER;
    float g = 0.f, u = 0.f;
    for (int p = 0; p < S; p++) {
        g += part[(size_t)p*B_*2*INTER + gi];
        u += part[(size_t)p*B_*2*INTER + ui];
    }
    out[i] = (g / (1.f + __expf(-g))) * u;
}

// ---------------- launch ----------------------------------------------------
extern "C" void kernel_launch(void* const* d_in, const int* in_sizes, int n_in,
                              void* d_out, int out_size)
{
    const int*   positions    = (const int*)  d_in[0];
    const float* hidden       = (const float*)d_in[1];
    const float* residual     = (const float*)d_in[2];
    const float* kv_cache     = (const float*)d_in[3];
    const int*   block_tables = (const int*)  d_in[4];
    const int*   slot_mapping = (const int*)  d_in[5];
    const int*   seq_lens     = (const int*)  d_in[6];
    // d_in[7] = is_prefill (statically 0)
    const float* w_qkv = (const float*)d_in[8];
    const float* b_qkv = (const float*)d_in[9];
    const float* w_o   = (const float*)d_in[10];
    const float* ln1   = (const float*)d_in[11];
    const float* ln2   = (const float*)d_in[12];
    const float* w_gu  = (const float*)d_in[13];
    const float* w_dn  = (const float*)d_in[14];
    float* out = (float*)d_out;   // [h (B*HID) | res2 (B*HID)]

    float *res1, *hn, *hn2, *qkv, *attn, *tmp, *act, *part;
    cudaGetSymbolAddress((void**)&res1, g_res1);
    cudaGetSymbolAddress((void**)&hn,   g_hn);
    cudaGetSymbolAddress((void**)&hn2,  g_hn2);
    cudaGetSymbolAddress((void**)&qkv,  g_qkv);
    cudaGetSymbolAddress((void**)&attn, g_attn);
    cudaGetSymbolAddress((void**)&tmp,  g_tmp);
    cudaGetSymbolAddress((void**)&act,  g_act);
    cudaGetSymbolAddress((void**)&part, g_part);

    // 1. res1 = hidden + residual ; hn = rmsnorm(res1)*ln1
    addnorm_kernel<<<B_, 256>>>(hidden, residual, ln1, res1, hn);

    // 2. qkv GEMM (split-K 8: 16x8 = 128 blocks, klen 192)
    gemm_f32<<<dim3(QKVN/128, 8), 256>>>(hn, w_qkv, part, HID, QKVN, 192);

    // 3. fused reduce + bias + RoPE
    qkv_finish_kernel<<<B_, 256>>>(part, b_qkv, positions, qkv, 8);

    // 4. paged GQA decode attention  (<- ncu -s 5 slot)
    attn_kernel<<<B_*NKV, 512>>>(qkv, kv_cache, block_tables, slot_mapping,
                                 seq_lens, attn);

    // 5. o-proj (split-K 12: 12x12 = 144 blocks, klen 128)
    gemm_f32<<<dim3(HID/128, 12), 256>>>(attn, w_o, part, QSZ, HID, 128);
    reduce_kernel<<<(B_*HID + 255)/256, 256>>>(part, nullptr, tmp, B_*HID, HID, 12);

    // 6. res2 = o + res1 (-> out second half) ; hn2 = rmsnorm(res2)*ln2
    addnorm_kernel<<<B_, 256>>>(tmp, res1, ln2, out + B_*HID, hn2);

    // 7. gate_up GEMM (140 blocks, no split) + fused SwiGLU
    gemm_f32<<<dim3(2*INTER/128, 1), 256>>>(hn2, w_gu, part, HID, 2*INTER, HID);
    act_reduce_kernel<<<(B_*INTER + 255)/256, 256>>>(part, act, 1);

    // 8. down GEMM (split-K 14: 12x14 = 168 blocks, klen 640) -> out first half
    gemm_f32<<<dim3(HID/128, 14), 256>>>(act, w_dn, part, INTER, HID, 640);
    reduce_kernel<<<(B_*HID + 255)/256, 256>>>(part, nullptr, out, B_*HID, HID, 14);
}